// round 11
// baseline (speedup 1.0000x reference)
#include <cuda_runtime.h>
#include <math.h>

#define ULL unsigned long long

// ---------------- problem constants ----------------
#define BB    16
#define INC   1024
#define PP    256
#define NN    1024      // 32*32
#define NHEAD 4
#define DD    64

// ---------------- scratch (device globals; no allocation allowed) --------
__device__ __align__(128) float g_ds [BB*PP*NN];
__device__ __align__(128) float g_q  [BB*PP*NN];
__device__ __align__(128) float g_k  [BB*PP*NN];
__device__ __align__(128) float g_v  [BB*PP*NN];
__device__ __align__(128) float g_o  [BB*PP*NN];
__device__ __align__(128) float g_y  [BB*PP*NN];
__device__ __align__(128) float g_pos[PP*NN];
__device__ __align__(128) float g_attn[67108864]; // 64 * 1024 * 1024

// ---------------- f32x2 packed-FMA helpers ----------------
__device__ __forceinline__ ULL dupf(float v) {
    ULL d; unsigned u = __float_as_uint(v);
    asm("mov.b64 %0, {%1, %1};" : "=l"(d) : "r"(u));
    return d;
}
__device__ __forceinline__ ULL fma2(ULL a, ULL b, ULL c) {
    ULL d;
    asm("fma.rn.f32x2 %0, %1, %2, %3;" : "=l"(d) : "l"(a), "l"(b), "l"(c));
    return d;
}
__device__ __forceinline__ float2 unpk(ULL v) {
    unsigned lo, hi;
    asm("mov.b64 {%0, %1}, %2;" : "=r"(lo), "=r"(hi) : "l"(v));
    return make_float2(__uint_as_float(lo), __uint_as_float(hi));
}

// ---------------- shared MMA core ----------------
// As2: [16][(BM+2)] ULL, each entry = value duplicated into both f32 halves.
// Bs : [16][128] float.
// Thread (tx,ty) computes rows ty*TM..+TM-1, cols {tx*4..+3} and {64+tx*4..+3}.
template<int TM, int BM>
__device__ __forceinline__ void mma16(const ULL* As2, const float* Bs,
                                      ULL (&acc)[TM][4], int ty, int tx) {
#pragma unroll
    for (int kk = 0; kk < 16; ++kk) {
        const ULL*   ar = As2 + kk * (BM + 2) + ty * TM;
        const float* br = Bs  + kk * 128;
        ULL a[TM];
#pragma unroll
        for (int i2 = 0; i2 < TM / 2; ++i2) {
            ulonglong2 t = *(const ulonglong2*)(ar + 2 * i2);
            a[2 * i2] = t.x; a[2 * i2 + 1] = t.y;
        }
        ulonglong2 b0 = ((const ulonglong2*)br)[tx];        // cols tx*4 .. tx*4+3
        ulonglong2 b1 = ((const ulonglong2*)br)[16 + tx];   // cols 64+tx*4 ..
        ULL b[4] = { b0.x, b0.y, b1.x, b1.y };
#pragma unroll
        for (int i = 0; i < TM; ++i)
#pragma unroll
            for (int j = 0; j < 4; ++j)
                acc[i][j] = fma2(a[i], b[j], acc[i][j]);
    }
}

// ---------------- kernel 1: downsample  C = w_ds @ x_b ----------------
// grid (8, 2, 16), 256 thr.  M=256, N=1024, K=1024
__global__ void __launch_bounds__(256, 2)
k_gemm_ds(const float* __restrict__ W, const float* __restrict__ X) {
    const int b  = blockIdx.z;
    const float* A  = W;                           // [256 x 1024] row-major
    const float* Bm = X + (size_t)b * INC * NN;    // [1024 x 1024]
    float*       C  = g_ds + (size_t)b * PP * NN;
    const int m0 = blockIdx.y * 128, n0 = blockIdx.x * 128;
    __shared__ __align__(16) ULL   As2[16 * 130];
    __shared__ __align__(16) float Bs [16 * 128];
    ULL acc[8][4];
#pragma unroll
    for (int i = 0; i < 8; ++i)
#pragma unroll
        for (int j = 0; j < 4; ++j) acc[i][j] = 0ull;
    const int tid = threadIdx.x, tx = tid & 15, ty = tid >> 4;
#pragma unroll 1
    for (int k0 = 0; k0 < 1024; k0 += 16) {
#pragma unroll
        for (int t = tid; t < 2048; t += 256) {
            int mm = t >> 4, kk = t & 15;
            As2[kk * 130 + mm] = dupf(A[(size_t)(m0 + mm) * 1024 + k0 + kk]);
        }
#pragma unroll
        for (int t = tid; t < 2048; t += 256) {
            int nn = t & 127, kk = t >> 7;
            Bs[kk * 128 + nn] = Bm[(size_t)(k0 + kk) * 1024 + n0 + nn];
        }
        __syncthreads();
        mma16<8, 128>(As2, Bs, acc, ty, tx);
        __syncthreads();
    }
#pragma unroll
    for (int i = 0; i < 8; ++i) {
        int m = m0 + ty * 8 + i;
        float2 p0 = unpk(acc[i][0]), p1 = unpk(acc[i][1]);
        float2 p2 = unpk(acc[i][2]), p3 = unpk(acc[i][3]);
        *(float4*)(C + (size_t)m * 1024 + n0 + tx * 4)      = make_float4(p0.x, p0.y, p1.x, p1.y);
        *(float4*)(C + (size_t)m * 1024 + n0 + 64 + tx * 4) = make_float4(p2.x, p2.y, p3.x, p3.y);
    }
}

// ---------------- kernel 2: q/k/v = W @ ds + b ----------------
// grid (8, 2, 48): z = b*3 + s.  M=256, N=1024, K=256
__global__ void __launch_bounds__(256, 2)
k_gemm_qkv(const float* __restrict__ wq, const float* __restrict__ wk,
           const float* __restrict__ wv, const float* __restrict__ bq,
           const float* __restrict__ bk, const float* __restrict__ bv) {
    const int b = blockIdx.z / 3, s = blockIdx.z % 3;
    const float* A    = (s == 0) ? wq : (s == 1) ? wk : wv;   // [256 x 256]
    const float* bias = (s == 0) ? bq : (s == 1) ? bk : bv;
    const float* Bm   = g_ds + (size_t)b * PP * NN;
    float*       C    = ((s == 0) ? g_q : (s == 1) ? g_k : g_v) + (size_t)b * PP * NN;
    const int m0 = blockIdx.y * 128, n0 = blockIdx.x * 128;
    __shared__ __align__(16) ULL   As2[16 * 130];
    __shared__ __align__(16) float Bs [16 * 128];
    ULL acc[8][4];
#pragma unroll
    for (int i = 0; i < 8; ++i)
#pragma unroll
        for (int j = 0; j < 4; ++j) acc[i][j] = 0ull;
    const int tid = threadIdx.x, tx = tid & 15, ty = tid >> 4;
#pragma unroll 1
    for (int k0 = 0; k0 < 256; k0 += 16) {
#pragma unroll
        for (int t = tid; t < 2048; t += 256) {
            int mm = t >> 4, kk = t & 15;
            As2[kk * 130 + mm] = dupf(A[(m0 + mm) * 256 + k0 + kk]);
        }
#pragma unroll
        for (int t = tid; t < 2048; t += 256) {
            int nn = t & 127, kk = t >> 7;
            Bs[kk * 128 + nn] = Bm[(size_t)(k0 + kk) * 1024 + n0 + nn];
        }
        __syncthreads();
        mma16<8, 128>(As2, Bs, acc, ty, tx);
        __syncthreads();
    }
#pragma unroll
    for (int i = 0; i < 8; ++i) {
        int m = m0 + ty * 8 + i;
        float bv_ = bias[m];
        float2 p0 = unpk(acc[i][0]), p1 = unpk(acc[i][1]);
        float2 p2 = unpk(acc[i][2]), p3 = unpk(acc[i][3]);
        *(float4*)(C + (size_t)m * 1024 + n0 + tx * 4) =
            make_float4(p0.x + bv_, p0.y + bv_, p1.x + bv_, p1.y + bv_);
        *(float4*)(C + (size_t)m * 1024 + n0 + 64 + tx * 4) =
            make_float4(p2.x + bv_, p2.y + bv_, p3.x + bv_, p3.y + bv_);
    }
}

// ---------------- kernel 3: pos[h*64+d][n] = rel_w[h,d,w] + rel_h[h,d,hh] ----
__global__ void k_pos(const float* __restrict__ rel_h, const float* __restrict__ rel_w) {
    int idx = blockIdx.x * 256 + threadIdx.x;   // < 256*1024
    int n = idx & 1023, p = idx >> 10;
    int w = n >> 5, hh = n & 31;
    g_pos[idx] = rel_w[p * 32 + w] + rel_h[p * 32 + hh];
}

// ---------------- kernel 4: logits (TN gemm, 2 K-segments of 64) ----------
// logit[i,j] = sum_d q[d,i]k[d,j] + sum_d pos[d,i]q[d,j]
// grid (8, 8, 64): z = b*4+h.  M=N=1024, K=128
__global__ void __launch_bounds__(256, 2)
k_gemm_logits() {
    const int z = blockIdx.z, h = z & 3;
    const float* Aseg[2] = { g_q + (size_t)z * 65536, g_pos + (size_t)h * 65536 };
    const float* Bseg[2] = { g_k + (size_t)z * 65536, g_q  + (size_t)z * 65536 };
    float* C = g_attn + (size_t)z * 1048576;
    const int m0 = blockIdx.y * 128, n0 = blockIdx.x * 128;
    __shared__ __align__(16) ULL   As2[16 * 130];
    __shared__ __align__(16) float Bs [16 * 128];
    ULL acc[8][4];
#pragma unroll
    for (int i = 0; i < 8; ++i)
#pragma unroll
        for (int j = 0; j < 4; ++j) acc[i][j] = 0ull;
    const int tid = threadIdx.x, tx = tid & 15, ty = tid >> 4;
    for (int seg = 0; seg < 2; ++seg) {
        const float* Ap = Aseg[seg];
        const float* Bp = Bseg[seg];
#pragma unroll 1
        for (int k0 = 0; k0 < 64; k0 += 16) {
#pragma unroll
            for (int t = tid; t < 2048; t += 256) {
                int mm = t & 127, kk = t >> 7;
                As2[kk * 130 + mm] = dupf(Ap[(size_t)(k0 + kk) * 1024 + m0 + mm]);
            }
#pragma unroll
            for (int t = tid; t < 2048; t += 256) {
                int nn = t & 127, kk = t >> 7;
                Bs[kk * 128 + nn] = Bp[(size_t)(k0 + kk) * 1024 + n0 + nn];
            }
            __syncthreads();
            mma16<8, 128>(As2, Bs, acc, ty, tx);
            __syncthreads();
        }
    }
#pragma unroll
    for (int i = 0; i < 8; ++i) {
        int m = m0 + ty * 8 + i;
        float2 p0 = unpk(acc[i][0]), p1 = unpk(acc[i][1]);
        float2 p2 = unpk(acc[i][2]), p3 = unpk(acc[i][3]);
        *(float4*)(C + (size_t)m * 1024 + n0 + tx * 4)      = make_float4(p0.x, p0.y, p1.x, p1.y);
        *(float4*)(C + (size_t)m * 1024 + n0 + 64 + tx * 4) = make_float4(p2.x, p2.y, p3.x, p3.y);
    }
}

// ---------------- kernel 5: row softmax, in-place on g_attn ----------------
// grid 65536, 256 thr; each thread owns 4 contiguous floats of one row.
__global__ void k_softmax() {
    const size_t row = blockIdx.x;
    float4* p = reinterpret_cast<float4*>(g_attn + row * 1024);
    const int tid = threadIdx.x;
    float4 v = p[tid];
    float m = fmaxf(fmaxf(v.x, v.y), fmaxf(v.z, v.w));
#pragma unroll
    for (int o = 16; o; o >>= 1) m = fmaxf(m, __shfl_xor_sync(0xffffffffu, m, o));
    __shared__ float sm[8], ss[8];
    if ((tid & 31) == 0) sm[tid >> 5] = m;
    __syncthreads();
    float bm = sm[0];
#pragma unroll
    for (int i = 1; i < 8; ++i) bm = fmaxf(bm, sm[i]);
    v.x = __expf(v.x - bm); v.y = __expf(v.y - bm);
    v.z = __expf(v.z - bm); v.w = __expf(v.w - bm);
    float s = v.x + v.y + v.z + v.w;
#pragma unroll
    for (int o = 16; o; o >>= 1) s += __shfl_xor_sync(0xffffffffu, s, o);
    if ((tid & 31) == 0) ss[tid >> 5] = s;
    __syncthreads();
    float bs = 0.f;
#pragma unroll
    for (int i = 0; i < 8; ++i) bs += ss[i];
    float inv = 1.0f / bs;
    v.x *= inv; v.y *= inv; v.z *= inv; v.w *= inv;
    p[tid] = v;
}

// ---------------- kernel 6: PV  o[d,i] = sum_j v[d,j] attn[i,j] -------------
// NT gemm: A = v [64 x 1024] row-major, B = attn [1024(i) x 1024(j)] (B^T use)
// grid (8, 1, 64).  M=64, N=1024, K=1024.  TM=4.
__global__ void __launch_bounds__(256, 2)
k_gemm_pv() {
    const int z = blockIdx.z;
    const float* A  = g_v    + (size_t)z * 65536;
    const float* Bm = g_attn + (size_t)z * 1048576;
    float*       C  = g_o    + (size_t)z * 65536;
    const int n0 = blockIdx.x * 128;
    __shared__ __align__(16) ULL   As2[16 * 66];
    __shared__ __align__(16) float Bs [16 * 128];
    ULL acc[4][4];
#pragma unroll
    for (int i = 0; i < 4; ++i)
#pragma unroll
        for (int j = 0; j < 4; ++j) acc[i][j] = 0ull;
    const int tid = threadIdx.x, tx = tid & 15, ty = tid >> 4;
#pragma unroll 1
    for (int k0 = 0; k0 < 1024; k0 += 16) {
#pragma unroll
        for (int t = tid; t < 1024; t += 256) {
            int mm = t >> 4, kk = t & 15;
            As2[kk * 66 + mm] = dupf(A[(size_t)mm * 1024 + k0 + kk]);
        }
#pragma unroll
        for (int t = tid; t < 2048; t += 256) {
            int kk = t & 15, nn = t >> 4;
            Bs[kk * 128 + nn] = Bm[(size_t)(n0 + nn) * 1024 + k0 + kk];
        }
        __syncthreads();
        mma16<4, 64>(As2, Bs, acc, ty, tx);
        __syncthreads();
    }
#pragma unroll
    for (int i = 0; i < 4; ++i) {
        int m = ty * 4 + i;   // d
        float2 p0 = unpk(acc[i][0]), p1 = unpk(acc[i][1]);
        float2 p2 = unpk(acc[i][2]), p3 = unpk(acc[i][3]);
        *(float4*)(C + (size_t)m * 1024 + n0 + tx * 4)      = make_float4(p0.x, p0.y, p1.x, p1.y);
        *(float4*)(C + (size_t)m * 1024 + n0 + 64 + tx * 4) = make_float4(p2.x, p2.y, p3.x, p3.y);
    }
}

// ---------------- kernel 7: LayerNorm over P=256 channels per pixel --------
// grid (32, 16): 32 pixels per block, block = (32 lanes) x (8 c-groups)
__global__ void __launch_bounds__(256)
k_layernorm(const float* __restrict__ lnw, const float* __restrict__ lnb) {
    const int b = blockIdx.y, n0 = blockIdx.x * 32;
    const int tx = threadIdx.x & 31, ty = threadIdx.x >> 5;
    __shared__ float s[256][33];
    __shared__ float rs[8][32], rq[8][32], mu_s[32], ri_s[32];
    const float* src = g_o + (size_t)b * PP * NN;
    for (int c = ty; c < 256; c += 8) s[c][tx] = src[(size_t)c * 1024 + n0 + tx];
    __syncthreads();
    float sm = 0.f, sq = 0.f;
    for (int c = ty; c < 256; c += 8) { float v = s[c][tx]; sm += v; sq += v * v; }
    rs[ty][tx] = sm; rq[ty][tx] = sq;
    __syncthreads();
    if (ty == 0) {
        float S = 0.f, Q = 0.f;
#pragma unroll
        for (int i = 0; i < 8; ++i) { S += rs[i][tx]; Q += rq[i][tx]; }
        float mu = S * (1.0f / 256.0f);
        float var = Q * (1.0f / 256.0f) - mu * mu;
        mu_s[tx] = mu;
        ri_s[tx] = rsqrtf(var + 1e-6f);
    }
    __syncthreads();
    float mu = mu_s[tx], ri = ri_s[tx];
    float* dst = g_y + (size_t)b * PP * NN;
    for (int c = ty; c < 256; c += 8) {
        float v = s[c][tx];
        dst[(size_t)c * 1024 + n0 + tx] = (v - mu) * ri * lnw[c] + lnb[c];
    }
}

// ---------------- kernel 8: expand + exact GELU + residual ------------------
// grid (8, 8, 16).  M=1024, N=1024, K=256
__global__ void __launch_bounds__(256, 2)
k_gemm_expand(const float* __restrict__ W1, const float* __restrict__ X,
              float* __restrict__ out) {
    const int b = blockIdx.z;
    const float* A  = W1;                          // [1024 x 256]
    const float* Bm = g_y + (size_t)b * PP * NN;
    float*       C  = out + (size_t)b * INC * NN;
    const float* Xr = X   + (size_t)b * INC * NN;
    const int m0 = blockIdx.y * 128, n0 = blockIdx.x * 128;
    __shared__ __align__(16) ULL   As2[16 * 130];
    __shared__ __align__(16) float Bs [16 * 128];
    ULL acc[8][4];
#pragma unroll
    for (int i = 0; i < 8; ++i)
#pragma unroll
        for (int j = 0; j < 4; ++j) acc[i][j] = 0ull;
    const int tid = threadIdx.x, tx = tid & 15, ty = tid >> 4;
#pragma unroll 1
    for (int k0 = 0; k0 < 256; k0 += 16) {
#pragma unroll
        for (int t = tid; t < 2048; t += 256) {
            int mm = t >> 4, kk = t & 15;
            As2[kk * 130 + mm] = dupf(A[(m0 + mm) * 256 + k0 + kk]);
        }
#pragma unroll
        for (int t = tid; t < 2048; t += 256) {
            int nn = t & 127, kk = t >> 7;
            Bs[kk * 128 + nn] = Bm[(size_t)(k0 + kk) * 1024 + n0 + nn];
        }
        __syncthreads();
        mma16<8, 128>(As2, Bs, acc, ty, tx);
        __syncthreads();
    }
#pragma unroll
    for (int i = 0; i < 8; ++i) {
        int m = m0 + ty * 8 + i;
        float g[8];
        float2 pp[4] = { unpk(acc[i][0]), unpk(acc[i][1]), unpk(acc[i][2]), unpk(acc[i][3]) };
        g[0] = pp[0].x; g[1] = pp[0].y; g[2] = pp[1].x; g[3] = pp[1].y;
        g[4] = pp[2].x; g[5] = pp[2].y; g[6] = pp[3].x; g[7] = pp[3].y;
#pragma unroll
        for (int u = 0; u < 8; ++u)
            g[u] = 0.5f * g[u] * (1.0f + erff(g[u] * 0.70710678118654752440f));
        size_t base = (size_t)m * 1024;
        float4 x0 = *(const float4*)(Xr + base + n0 + tx * 4);
        float4 x1 = *(const float4*)(Xr + base + n0 + 64 + tx * 4);
        *(float4*)(C + base + n0 + tx * 4)      = make_float4(g[0] + x0.x, g[1] + x0.y, g[2] + x0.z, g[3] + x0.w);
        *(float4*)(C + base + n0 + 64 + tx * 4) = make_float4(g[4] + x1.x, g[5] + x1.y, g[6] + x1.z, g[7] + x1.w);
    }
}

// ---------------- launch ----------------
extern "C" void kernel_launch(void* const* d_in, const int* in_sizes, int n_in,
                              void* d_out, int out_size) {
    const float* x     = (const float*)d_in[0];
    const float* w_ds  = (const float*)d_in[1];
    const float* wq    = (const float*)d_in[2];
    const float* bq    = (const float*)d_in[3];
    const float* wk    = (const float*)d_in[4];
    const float* bk    = (const float*)d_in[5];
    const float* wv    = (const float*)d_in[6];
    const float* bv    = (const float*)d_in[7];
    const float* rel_h = (const float*)d_in[8];
    const float* rel_w = (const float*)d_in[9];
    const float* lnw   = (const float*)d_in[10];
    const float* lnb   = (const float*)d_in[11];
    const float* w1    = (const float*)d_in[12];
    float* out = (float*)d_out;

    k_gemm_ds    <<<dim3(8, 2, 16), 256>>>(w_ds, x);
    k_pos        <<<1024, 256>>>(rel_h, rel_w);
    k_gemm_qkv   <<<dim3(8, 2, 48), 256>>>(wq, wk, wv, bq, bk, bv);
    k_gemm_logits<<<dim3(8, 8, 64), 256>>>();
    k_softmax    <<<65536, 256>>>();
    k_gemm_pv    <<<dim3(8, 1, 64), 256>>>();
    k_layernorm  <<<dim3(32, 16), 256>>>(lnw, lnb);
    k_gemm_expand<<<dim3(8, 8, 16), 256>>>(w1, x, out);
}

// round 12
// speedup vs baseline: 1.0034x; 1.0034x over previous
#include <cuda_runtime.h>
#include <math.h>

#define ULL unsigned long long

// ---------------- problem constants ----------------
#define BB    16
#define INC   1024
#define PP    256
#define NN    1024      // 32*32
#define NHEAD 4
#define DD    64

// ---------------- scratch (device globals; no allocation allowed) --------
__device__ __align__(128) float g_ds [BB*PP*NN];
__device__ __align__(128) float g_q  [BB*PP*NN];
__device__ __align__(128) float g_k  [BB*PP*NN];
__device__ __align__(128) float g_v  [BB*PP*NN];
__device__ __align__(128) float g_o  [BB*PP*NN];
__device__ __align__(128) float g_y  [BB*PP*NN];
__device__ __align__(128) float g_pos[PP*NN];
__device__ __align__(128) float g_attn[67108864]; // 64 * 1024 * 1024

// ---------------- f32x2 packed-FMA helpers ----------------
__device__ __forceinline__ ULL dupf(float v) {
    ULL d; unsigned u = __float_as_uint(v);
    asm("mov.b64 %0, {%1, %1};" : "=l"(d) : "r"(u));
    return d;
}
__device__ __forceinline__ ULL fma2(ULL a, ULL b, ULL c) {
    ULL d;
    asm("fma.rn.f32x2 %0, %1, %2, %3;" : "=l"(d) : "l"(a), "l"(b), "l"(c));
    return d;
}
__device__ __forceinline__ float2 unpk(ULL v) {
    unsigned lo, hi;
    asm("mov.b64 {%0, %1}, %2;" : "=r"(lo), "=r"(hi) : "l"(v));
    return make_float2(__uint_as_float(lo), __uint_as_float(hi));
}

// ---------------- shared MMA core ----------------
// As2: [16][(BM+2)] ULL, each entry = value duplicated into both f32 halves.
// Bs : [16][128] float.
// Thread (tx,ty) computes rows ty*TM..+TM-1, cols {tx*4..+3} and {64+tx*4..+3}.
template<int TM, int BM>
__device__ __forceinline__ void mma16(const ULL* As2, const float* Bs,
                                      ULL (&acc)[TM][4], int ty, int tx) {
#pragma unroll
    for (int kk = 0; kk < 16; ++kk) {
        const ULL*   ar = As2 + kk * (BM + 2) + ty * TM;
        const float* br = Bs  + kk * 128;
        ULL a[TM];
#pragma unroll
        for (int i2 = 0; i2 < TM / 2; ++i2) {
            ulonglong2 t = *(const ulonglong2*)(ar + 2 * i2);
            a[2 * i2] = t.x; a[2 * i2 + 1] = t.y;
        }
        ulonglong2 b0 = ((const ulonglong2*)br)[tx];        // cols tx*4 .. tx*4+3
        ulonglong2 b1 = ((const ulonglong2*)br)[16 + tx];   // cols 64+tx*4 ..
        ULL b[4] = { b0.x, b0.y, b1.x, b1.y };
#pragma unroll
        for (int i = 0; i < TM; ++i)
#pragma unroll
            for (int j = 0; j < 4; ++j)
                acc[i][j] = fma2(a[i], b[j], acc[i][j]);
    }
}

// ---------------- kernel 1: downsample  C = w_ds @ x_b ----------------
// grid (8, 2, 16), 256 thr.  M=256, N=1024, K=1024
__global__ void __launch_bounds__(256, 2)
k_gemm_ds(const float* __restrict__ W, const float* __restrict__ X) {
    const int b  = blockIdx.z;
    const float* A  = W;                           // [256 x 1024] row-major
    const float* Bm = X + (size_t)b * INC * NN;    // [1024 x 1024]
    float*       C  = g_ds + (size_t)b * PP * NN;
    const int m0 = blockIdx.y * 128, n0 = blockIdx.x * 128;
    __shared__ __align__(16) ULL   As2[16 * 130];
    __shared__ __align__(16) float Bs [16 * 128];
    ULL acc[8][4];
#pragma unroll
    for (int i = 0; i < 8; ++i)
#pragma unroll
        for (int j = 0; j < 4; ++j) acc[i][j] = 0ull;
    const int tid = threadIdx.x, tx = tid & 15, ty = tid >> 4;
#pragma unroll 1
    for (int k0 = 0; k0 < 1024; k0 += 16) {
#pragma unroll
        for (int t = tid; t < 2048; t += 256) {
            int mm = t >> 4, kk = t & 15;
            As2[kk * 130 + mm] = dupf(A[(size_t)(m0 + mm) * 1024 + k0 + kk]);
        }
#pragma unroll
        for (int t = tid; t < 2048; t += 256) {
            int nn = t & 127, kk = t >> 7;
            Bs[kk * 128 + nn] = Bm[(size_t)(k0 + kk) * 1024 + n0 + nn];
        }
        __syncthreads();
        mma16<8, 128>(As2, Bs, acc, ty, tx);
        __syncthreads();
    }
#pragma unroll
    for (int i = 0; i < 8; ++i) {
        int m = m0 + ty * 8 + i;
        float2 p0 = unpk(acc[i][0]), p1 = unpk(acc[i][1]);
        float2 p2 = unpk(acc[i][2]), p3 = unpk(acc[i][3]);
        *(float4*)(C + (size_t)m * 1024 + n0 + tx * 4)      = make_float4(p0.x, p0.y, p1.x, p1.y);
        *(float4*)(C + (size_t)m * 1024 + n0 + 64 + tx * 4) = make_float4(p2.x, p2.y, p3.x, p3.y);
    }
}

// ---------------- kernel 2: q/k/v = W @ ds + b ----------------
// grid (8, 2, 48): z = b*3 + s.  M=256, N=1024, K=256
__global__ void __launch_bounds__(256, 2)
k_gemm_qkv(const float* __restrict__ wq, const float* __restrict__ wk,
           const float* __restrict__ wv, const float* __restrict__ bq,
           const float* __restrict__ bk, const float* __restrict__ bv) {
    const int b = blockIdx.z / 3, s = blockIdx.z % 3;
    const float* A    = (s == 0) ? wq : (s == 1) ? wk : wv;   // [256 x 256]
    const float* bias = (s == 0) ? bq : (s == 1) ? bk : bv;
    const float* Bm   = g_ds + (size_t)b * PP * NN;
    float*       C    = ((s == 0) ? g_q : (s == 1) ? g_k : g_v) + (size_t)b * PP * NN;
    const int m0 = blockIdx.y * 128, n0 = blockIdx.x * 128;
    __shared__ __align__(16) ULL   As2[16 * 130];
    __shared__ __align__(16) float Bs [16 * 128];
    ULL acc[8][4];
#pragma unroll
    for (int i = 0; i < 8; ++i)
#pragma unroll
        for (int j = 0; j < 4; ++j) acc[i][j] = 0ull;
    const int tid = threadIdx.x, tx = tid & 15, ty = tid >> 4;
#pragma unroll 1
    for (int k0 = 0; k0 < 256; k0 += 16) {
#pragma unroll
        for (int t = tid; t < 2048; t += 256) {
            int mm = t >> 4, kk = t & 15;
            As2[kk * 130 + mm] = dupf(A[(m0 + mm) * 256 + k0 + kk]);
        }
#pragma unroll
        for (int t = tid; t < 2048; t += 256) {
            int nn = t & 127, kk = t >> 7;
            Bs[kk * 128 + nn] = Bm[(size_t)(k0 + kk) * 1024 + n0 + nn];
        }
        __syncthreads();
        mma16<8, 128>(As2, Bs, acc, ty, tx);
        __syncthreads();
    }
#pragma unroll
    for (int i = 0; i < 8; ++i) {
        int m = m0 + ty * 8 + i;
        float bv_ = bias[m];
        float2 p0 = unpk(acc[i][0]), p1 = unpk(acc[i][1]);
        float2 p2 = unpk(acc[i][2]), p3 = unpk(acc[i][3]);
        *(float4*)(C + (size_t)m * 1024 + n0 + tx * 4) =
            make_float4(p0.x + bv_, p0.y + bv_, p1.x + bv_, p1.y + bv_);
        *(float4*)(C + (size_t)m * 1024 + n0 + 64 + tx * 4) =
            make_float4(p2.x + bv_, p2.y + bv_, p3.x + bv_, p3.y + bv_);
    }
}

// ---------------- kernel 3: pos[h*64+d][n] = rel_w[h,d,w] + rel_h[h,d,hh] ----
__global__ void k_pos(const float* __restrict__ rel_h, const float* __restrict__ rel_w) {
    int idx = blockIdx.x * 256 + threadIdx.x;   // < 256*1024
    int n = idx & 1023, p = idx >> 10;
    int w = n >> 5, hh = n & 31;
    g_pos[idx] = rel_w[p * 32 + w] + rel_h[p * 32 + hh];
}

// ---------------- kernel 4: logits (TN gemm, 2 K-segments of 64) ----------
// logit[i,j] = sum_d q[d,i]k[d,j] + sum_d pos[d,i]q[d,j]
// grid (8, 8, 64): z = b*4+h.  M=N=1024, K=128
__global__ void __launch_bounds__(256, 2)
k_gemm_logits() {
    const int z = blockIdx.z, h = z & 3;
    const float* Aseg[2] = { g_q + (size_t)z * 65536, g_pos + (size_t)h * 65536 };
    const float* Bseg[2] = { g_k + (size_t)z * 65536, g_q  + (size_t)z * 65536 };
    float* C = g_attn + (size_t)z * 1048576;
    const int m0 = blockIdx.y * 128, n0 = blockIdx.x * 128;
    __shared__ __align__(16) ULL   As2[16 * 130];
    __shared__ __align__(16) float Bs [16 * 128];
    ULL acc[8][4];
#pragma unroll
    for (int i = 0; i < 8; ++i)
#pragma unroll
        for (int j = 0; j < 4; ++j) acc[i][j] = 0ull;
    const int tid = threadIdx.x, tx = tid & 15, ty = tid >> 4;
    for (int seg = 0; seg < 2; ++seg) {
        const float* Ap = Aseg[seg];
        const float* Bp = Bseg[seg];
#pragma unroll 1
        for (int k0 = 0; k0 < 64; k0 += 16) {
#pragma unroll
            for (int t = tid; t < 2048; t += 256) {
                int mm = t & 127, kk = t >> 7;
                As2[kk * 130 + mm] = dupf(Ap[(size_t)(k0 + kk) * 1024 + m0 + mm]);
            }
#pragma unroll
            for (int t = tid; t < 2048; t += 256) {
                int nn = t & 127, kk = t >> 7;
                Bs[kk * 128 + nn] = Bp[(size_t)(k0 + kk) * 1024 + n0 + nn];
            }
            __syncthreads();
            mma16<8, 128>(As2, Bs, acc, ty, tx);
            __syncthreads();
        }
    }
#pragma unroll
    for (int i = 0; i < 8; ++i) {
        int m = m0 + ty * 8 + i;
        float2 p0 = unpk(acc[i][0]), p1 = unpk(acc[i][1]);
        float2 p2 = unpk(acc[i][2]), p3 = unpk(acc[i][3]);
        *(float4*)(C + (size_t)m * 1024 + n0 + tx * 4)      = make_float4(p0.x, p0.y, p1.x, p1.y);
        *(float4*)(C + (size_t)m * 1024 + n0 + 64 + tx * 4) = make_float4(p2.x, p2.y, p3.x, p3.y);
    }
}

// ---------------- kernel 5: row softmax, in-place on g_attn ----------------
// grid 65536, 256 thr; each thread owns 4 contiguous floats of one row.
__global__ void k_softmax() {
    const size_t row = blockIdx.x;
    float4* p = reinterpret_cast<float4*>(g_attn + row * 1024);
    const int tid = threadIdx.x;
    float4 v = p[tid];
    float m = fmaxf(fmaxf(v.x, v.y), fmaxf(v.z, v.w));
#pragma unroll
    for (int o = 16; o; o >>= 1) m = fmaxf(m, __shfl_xor_sync(0xffffffffu, m, o));
    __shared__ float sm[8], ss[8];
    if ((tid & 31) == 0) sm[tid >> 5] = m;
    __syncthreads();
    float bm = sm[0];
#pragma unroll
    for (int i = 1; i < 8; ++i) bm = fmaxf(bm, sm[i]);
    v.x = __expf(v.x - bm); v.y = __expf(v.y - bm);
    v.z = __expf(v.z - bm); v.w = __expf(v.w - bm);
    float s = v.x + v.y + v.z + v.w;
#pragma unroll
    for (int o = 16; o; o >>= 1) s += __shfl_xor_sync(0xffffffffu, s, o);
    if ((tid & 31) == 0) ss[tid >> 5] = s;
    __syncthreads();
    float bs = 0.f;
#pragma unroll
    for (int i = 0; i < 8; ++i) bs += ss[i];
    float inv = 1.0f / bs;
    v.x *= inv; v.y *= inv; v.z *= inv; v.w *= inv;
    p[tid] = v;
}

// ---------------- kernel 6: PV  o[d,i] = sum_j v[d,j] attn[i,j] -------------
// NT gemm: A = v [64 x 1024] row-major, B = attn [1024(i) x 1024(j)] (B^T use)
// grid (8, 1, 64).  M=64, N=1024, K=1024.  TM=4.
__global__ void __launch_bounds__(256, 2)
k_gemm_pv() {
    const int z = blockIdx.z;
    const float* A  = g_v    + (size_t)z * 65536;
    const float* Bm = g_attn + (size_t)z * 1048576;
    float*       C  = g_o    + (size_t)z * 65536;
    const int n0 = blockIdx.x * 128;
    __shared__ __align__(16) ULL   As2[16 * 66];
    __shared__ __align__(16) float Bs [16 * 128];
    ULL acc[4][4];
#pragma unroll
    for (int i = 0; i < 4; ++i)
#pragma unroll
        for (int j = 0; j < 4; ++j) acc[i][j] = 0ull;
    const int tid = threadIdx.x, tx = tid & 15, ty = tid >> 4;
#pragma unroll 1
    for (int k0 = 0; k0 < 1024; k0 += 16) {
#pragma unroll
        for (int t = tid; t < 1024; t += 256) {
            int mm = t >> 4, kk = t & 15;
            As2[kk * 66 + mm] = dupf(A[(size_t)mm * 1024 + k0 + kk]);
        }
#pragma unroll
        for (int t = tid; t < 2048; t += 256) {
            int kk = t & 15, nn = t >> 4;
            Bs[kk * 128 + nn] = Bm[(size_t)(n0 + nn) * 1024 + k0 + kk];
        }
        __syncthreads();
        mma16<4, 64>(As2, Bs, acc, ty, tx);
        __syncthreads();
    }
#pragma unroll
    for (int i = 0; i < 4; ++i) {
        int m = ty * 4 + i;   // d
        float2 p0 = unpk(acc[i][0]), p1 = unpk(acc[i][1]);
        float2 p2 = unpk(acc[i][2]), p3 = unpk(acc[i][3]);
        *(float4*)(C + (size_t)m * 1024 + n0 + tx * 4)      = make_float4(p0.x, p0.y, p1.x, p1.y);
        *(float4*)(C + (size_t)m * 1024 + n0 + 64 + tx * 4) = make_float4(p2.x, p2.y, p3.x, p3.y);
    }
}

// ---------------- kernel 7: LayerNorm over P=256 channels per pixel --------
// grid (32, 16): 32 pixels per block, block = (32 lanes) x (8 c-groups)
__global__ void __launch_bounds__(256)
k_layernorm(const float* __restrict__ lnw, const float* __restrict__ lnb) {
    const int b = blockIdx.y, n0 = blockIdx.x * 32;
    const int tx = threadIdx.x & 31, ty = threadIdx.x >> 5;
    __shared__ float s[256][33];
    __shared__ float rs[8][32], rq[8][32], mu_s[32], ri_s[32];
    const float* src = g_o + (size_t)b * PP * NN;
    for (int c = ty; c < 256; c += 8) s[c][tx] = src[(size_t)c * 1024 + n0 + tx];
    __syncthreads();
    float sm = 0.f, sq = 0.f;
    for (int c = ty; c < 256; c += 8) { float v = s[c][tx]; sm += v; sq += v * v; }
    rs[ty][tx] = sm; rq[ty][tx] = sq;
    __syncthreads();
    if (ty == 0) {
        float S = 0.f, Q = 0.f;
#pragma unroll
        for (int i = 0; i < 8; ++i) { S += rs[i][tx]; Q += rq[i][tx]; }
        float mu = S * (1.0f / 256.0f);
        float var = Q * (1.0f / 256.0f) - mu * mu;
        mu_s[tx] = mu;
        ri_s[tx] = rsqrtf(var + 1e-6f);
    }
    __syncthreads();
    float mu = mu_s[tx], ri = ri_s[tx];
    float* dst = g_y + (size_t)b * PP * NN;
    for (int c = ty; c < 256; c += 8) {
        float v = s[c][tx];
        dst[(size_t)c * 1024 + n0 + tx] = (v - mu) * ri * lnw[c] + lnb[c];
    }
}

// ---------------- kernel 8: expand + exact GELU + residual ------------------
// grid (8, 8, 16).  M=1024, N=1024, K=256
__global__ void __launch_bounds__(256, 2)
k_gemm_expand(const float* __restrict__ W1, const float* __restrict__ X,
              float* __restrict__ out) {
    const int b = blockIdx.z;
    const float* A  = W1;                          // [1024 x 256]
    const float* Bm = g_y + (size_t)b * PP * NN;
    float*       C  = out + (size_t)b * INC * NN;
    const float* Xr = X   + (size_t)b * INC * NN;
    const int m0 = blockIdx.y * 128, n0 = blockIdx.x * 128;
    __shared__ __align__(16) ULL   As2[16 * 130];
    __shared__ __align__(16) float Bs [16 * 128];
    ULL acc[8][4];
#pragma unroll
    for (int i = 0; i < 8; ++i)
#pragma unroll
        for (int j = 0; j < 4; ++j) acc[i][j] = 0ull;
    const int tid = threadIdx.x, tx = tid & 15, ty = tid >> 4;
#pragma unroll 1
    for (int k0 = 0; k0 < 256; k0 += 16) {
#pragma unroll
        for (int t = tid; t < 2048; t += 256) {
            int mm = t >> 4, kk = t & 15;
            As2[kk * 130 + mm] = dupf(A[(m0 + mm) * 256 + k0 + kk]);
        }
#pragma unroll
        for (int t = tid; t < 2048; t += 256) {
            int nn = t & 127, kk = t >> 7;
            Bs[kk * 128 + nn] = Bm[(size_t)(k0 + kk) * 1024 + n0 + nn];
        }
        __syncthreads();
        mma16<8, 128>(As2, Bs, acc, ty, tx);
        __syncthreads();
    }
#pragma unroll
    for (int i = 0; i < 8; ++i) {
        int m = m0 + ty * 8 + i;
        float g[8];
        float2 pp[4] = { unpk(acc[i][0]), unpk(acc[i][1]), unpk(acc[i][2]), unpk(acc[i][3]) };
        g[0] = pp[0].x; g[1] = pp[0].y; g[2] = pp[1].x; g[3] = pp[1].y;
        g[4] = pp[2].x; g[5] = pp[2].y; g[6] = pp[3].x; g[7] = pp[3].y;
#pragma unroll
        for (int u = 0; u < 8; ++u)
            g[u] = 0.5f * g[u] * (1.0f + erff(g[u] * 0.70710678118654752440f));
        size_t base = (size_t)m * 1024;
        float4 x0 = *(const float4*)(Xr + base + n0 + tx * 4);
        float4 x1 = *(const float4*)(Xr + base + n0 + 64 + tx * 4);
        *(float4*)(C + base + n0 + tx * 4)      = make_float4(g[0] + x0.x, g[1] + x0.y, g[2] + x0.z, g[3] + x0.w);
        *(float4*)(C + base + n0 + 64 + tx * 4) = make_float4(g[4] + x1.x, g[5] + x1.y, g[6] + x1.z, g[7] + x1.w);
    }
}

// ---------------- launch ----------------
extern "C" void kernel_launch(void* const* d_in, const int* in_sizes, int n_in,
                              void* d_out, int out_size) {
    const float* x     = (const float*)d_in[0];
    const float* w_ds  = (const float*)d_in[1];
    const float* wq    = (const float*)d_in[2];
    const float* bq    = (const float*)d_in[3];
    const float* wk    = (const float*)d_in[4];
    const float* bk    = (const float*)d_in[5];
    const float* wv    = (const float*)d_in[6];
    const float* bv    = (const float*)d_in[7];
    const float* rel_h = (const float*)d_in[8];
    const float* rel_w = (const float*)d_in[9];
    const float* lnw   = (const float*)d_in[10];
    const float* lnb   = (const float*)d_in[11];
    const float* w1    = (const float*)d_in[12];
    float* out = (float*)d_out;

    k_gemm_ds    <<<dim3(8, 2, 16), 256>>>(w_ds, x);
    k_pos        <<<1024, 256>>>(rel_h, rel_w);
    k_gemm_qkv   <<<dim3(8, 2, 48), 256>>>(wq, wk, wv, bq, bk, bv);
    k_gemm_logits<<<dim3(8, 8, 64), 256>>>();
    k_softmax    <<<65536, 256>>>();
    k_gemm_pv    <<<dim3(8, 1, 64), 256>>>();
    k_layernorm  <<<dim3(32, 16), 256>>>(lnw, lnb);
    k_gemm_expand<<<dim3(8, 8, 16), 256>>>(w1, x, out);
}